// round 16
// baseline (speedup 1.0000x reference)
#include <cuda_runtime.h>
#include <cuda_fp16.h>
#include <math.h>
#include <stdint.h>

// Problem constants
constexpr int B_ = 4;
constexpr int S_ = 2048;
constexpr int E_ = 1024;
constexpr int H_ = 16;
constexpr int D_ = 64;
constexpr int M_ = B_ * S_;   // 8192 tokens

// Q pre-scale: 1/sqrt(64) * log2(e)  (softmax runs in base-2)
#define QSCALE 0.180336880f

// Scratch (allocation-free rule: __device__ globals)
__device__ __half g_xh[(long long)M_ * E_];          // x in fp16
__device__ __half g_qkvh[(long long)M_ * 2 * E_];    // Q(pre-scaled)|K, fp16
__device__ __half g_vth[(long long)E_ * M_];         // V transposed [h*64+d][token]
__device__ __half g_yh[(long long)M_ * E_];          // attention out, fp16
__device__ __half g_wTh[(long long)3 * E_ * E_ + (long long)E_ * E_]; // W^T fp16

__device__ __forceinline__ float ex2f(float x) {
    float r; asm("ex2.approx.f32 %0, %1;" : "=f"(r) : "f"(x)); return r;
}
__device__ __forceinline__ uint32_t h2ex2(uint32_t x) {   // ex2 on packed half2
    uint32_t r; asm("ex2.approx.f16x2 %0, %1;" : "=r"(r) : "r"(x)); return r;
}
__device__ __forceinline__ uint32_t pack_half2(float lo, float hi) {
    uint32_t r;
    asm("cvt.rn.f16x2.f32 %0, %1, %2;" : "=r"(r) : "f"(hi), "f"(lo));
    return r;
}
__device__ __forceinline__ uint32_t smem_u32(const void* p) {
    uint32_t a;
    asm("{ .reg .u64 t; cvta.to.shared.u64 t, %1; cvt.u32.u64 %0, t; }"
        : "=r"(a) : "l"(p));
    return a;
}

#define CP_ASYNC16(dst, src) \
    asm volatile("cp.async.cg.shared.global [%0], [%1], 16;" \
        :: "r"(dst), "l"(src))
#define CP_COMMIT() asm volatile("cp.async.commit_group;" ::: "memory")
#define CP_WAIT0()  asm volatile("cp.async.wait_group 0;" ::: "memory")
#define CP_WAIT1()  asm volatile("cp.async.wait_group 1;" ::: "memory")

#define LDSM_X4(r0, r1, r2, r3, addr) \
    asm volatile("ldmatrix.sync.aligned.m8n8.x4.shared.b16 {%0,%1,%2,%3}, [%4];" \
        : "=r"(r0), "=r"(r1), "=r"(r2), "=r"(r3) : "r"(addr))

// m16n8k16 fp16 MMA, fp32 accumulate (sm_80+; Blackwell tensor pipe)
__device__ __forceinline__ void mma_f16(float d[4], const uint32_t a[4],
                                        const uint32_t b[2]) {
    asm volatile(
        "mma.sync.aligned.m16n8k16.row.col.f32.f16.f16.f32 "
        "{%0,%1,%2,%3}, {%4,%5,%6,%7}, {%8,%9}, {%0,%1,%2,%3};\n"
        : "+f"(d[0]), "+f"(d[1]), "+f"(d[2]), "+f"(d[3])
        : "r"(a[0]), "r"(a[1]), "r"(a[2]), "r"(a[3]), "r"(b[0]), "r"(b[1]));
}

// ===========================================================================
// x -> fp16
// ===========================================================================
__global__ void __launch_bounds__(256) cvt_kernel(
    const float* __restrict__ X, __half* __restrict__ XH, long long n4) {
    long long i = blockIdx.x * 256 + threadIdx.x;
    long long stride = (long long)gridDim.x * 256;
    for (; i < n4; i += stride) {
        float4 v = ((const float4*)X)[i];
        ((uint2*)XH)[i] = make_uint2(pack_half2(v.x, v.y), pack_half2(v.z, v.w));
    }
}

// ===========================================================================
// Fused weight transpose + fp16 for BOTH weights in one launch.
// blocks x in [0,96): w_att (N=3072); [96,128): w_proj (N=1024). K=1024.
// ===========================================================================
__global__ void __launch_bounds__(256) transpose2_kernel(
    const float* __restrict__ Wa, __half* __restrict__ WaT,
    const float* __restrict__ Wp, __half* __restrict__ WpT) {
    __shared__ float t[32][33];
    const bool isA = (blockIdx.x < 96);
    const float* W = isA ? Wa : Wp;
    __half* WT     = isA ? WaT : WpT;
    const int N    = isA ? 3 * E_ : E_;
    const int n0   = (isA ? blockIdx.x : blockIdx.x - 96) * 32;
    const int k0   = blockIdx.y * 32;
    const int tx = threadIdx.x & 31, ty = threadIdx.x >> 5;
    for (int r = ty; r < 32; r += 8)
        t[r][tx] = W[(long long)(k0 + r) * N + n0 + tx];
    __syncthreads();
    for (int r = ty; r < 32; r += 8)
        WT[(long long)(n0 + r) * E_ + k0 + tx] = __float2half_rn(t[tx][r]);
}

// ===========================================================================
// fp16 mma.sync GEMM, 3-stage cp.async pipeline, ldmatrix fragment loads.
// C = A[M,K] @ BT[N,K]^T, fp16 operands, fp32 accum.
// 128x128x64 tile (BK=64 halves = 128B rows), 8 warps (2x4), warp 64x32.
// mode 0: fp32 out to Cf.
// mode 1 (QKV): n0<1024 -> Q (scale by QSCALE, half -> Ch);
//               n0<2048 -> K (half -> Ch); else V -> VT transposed.
// ===========================================================================
constexpr int BK = 64;                          // halves per chunk (128B)
constexpr int GSTAGE_B = 2 * 128 * 128;         // A + B tile bytes = 32768
constexpr int GEMM_SMEM_BYTES = 3 * GSTAGE_B;   // 98304

__device__ __forceinline__ void gemm_issue(
    const __half* __restrict__ A, const __half* __restrict__ BT,
    uint32_t sbase, int stage, int m0, int n0, int k0, int K, int tid) {
    uint32_t st = sbase + stage * GSTAGE_B;
#pragma unroll
    for (int it = 0; it < 4; it++) {
        int idx = tid + it * 256;          // 0..1023
        int row = idx >> 3;                // 0..127
        int c   = idx & 7;                 // 16B chunk
        uint32_t off = (uint32_t)(row * 8 + (c ^ (row & 7))) * 16;
        CP_ASYNC16(st + off, A + (long long)(m0 + row) * K + k0 + c * 8);
        CP_ASYNC16(st + 16384 + off, BT + (long long)(n0 + row) * K + k0 + c * 8);
    }
    CP_COMMIT();
}

__global__ void __launch_bounds__(256, 2) gemm_h_kernel(
    const __half* __restrict__ A, const __half* __restrict__ BT,
    float* __restrict__ Cf, __half* __restrict__ Ch, __half* __restrict__ VT,
    int M, int N, int K, int mode) {
    extern __shared__ char smc[];
    const uint32_t sbase = smem_u32(smc);

    const int tid  = threadIdx.x;
    const int wid  = tid >> 5;
    const int lane = tid & 31;
    const int gid  = lane >> 2;
    const int tig  = lane & 3;
    const int wm   = (wid & 1) * 64;
    const int wn   = (wid >> 1) * 32;
    const int m0   = blockIdx.y * 128;
    const int n0   = blockIdx.x * 128;

    const int rl = lane & 7;
    const uint32_t a_lane = (uint32_t)((wm + ((lane >> 3) & 1) * 8 + rl) * 128);
    const int a_cb = lane >> 4;
    const uint32_t b_lane = 16384u + (uint32_t)((wn + ((lane >> 4) & 1) * 8 + rl) * 128);
    const int b_cb = (lane >> 3) & 1;

    float acc[4][4][4] = {};

    const int NIT = K / BK;
    gemm_issue(A, BT, sbase, 0, m0, n0, 0, K, tid);
    gemm_issue(A, BT, sbase, 1, m0, n0, BK, K, tid);

    for (int i = 0; i < NIT; i++) {
        if (i + 1 < NIT) { CP_WAIT1(); } else { CP_WAIT0(); }
        __syncthreads();
        if (i + 2 < NIT)
            gemm_issue(A, BT, sbase, (i + 2) % 3, m0, n0, (i + 2) * BK, K, tid);

        const uint32_t stb = sbase + (uint32_t)(i % 3) * GSTAGE_B;
#pragma unroll
        for (int ks = 0; ks < 4; ks++) {       // 4 k16 steps per BK=64
            uint32_t af[4][4], bf[4][2];
#pragma unroll
            for (int mf = 0; mf < 4; mf++) {
                uint32_t ad = stb + a_lane + mf * 2048 +
                              ((uint32_t)((2 * ks + a_cb) ^ rl) << 4);
                LDSM_X4(af[mf][0], af[mf][1], af[mf][2], af[mf][3], ad);
            }
#pragma unroll
            for (int j = 0; j < 2; j++) {
                uint32_t bd = stb + b_lane + j * 2048 +
                              ((uint32_t)((2 * ks + b_cb) ^ rl) << 4);
                LDSM_X4(bf[2 * j][0], bf[2 * j][1], bf[2 * j + 1][0], bf[2 * j + 1][1], bd);
            }
#pragma unroll
            for (int mf = 0; mf < 4; mf++)
#pragma unroll
                for (int nf = 0; nf < 4; nf++)
                    mma_f16(acc[mf][nf], af[mf], bf[nf]);
        }
    }

    // epilogue
    if (mode == 0) {
#pragma unroll
        for (int mf = 0; mf < 4; mf++) {
            const int r0 = m0 + wm + mf * 16 + gid;
#pragma unroll
            for (int nf = 0; nf < 4; nf++) {
                const int c = n0 + wn + nf * 8 + 2 * tig;
                *(float2*)&Cf[(long long)r0 * N + c] =
                    make_float2(acc[mf][nf][0], acc[mf][nf][1]);
                *(float2*)&Cf[(long long)(r0 + 8) * N + c] =
                    make_float2(acc[mf][nf][2], acc[mf][nf][3]);
            }
        }
    } else {
        const int region = n0 >> 10;   // 0:Q 1:K 2:V
        if (region < 2) {
            const float s = (region == 0) ? QSCALE : 1.0f;
#pragma unroll
            for (int mf = 0; mf < 4; mf++) {
                const int r0 = m0 + wm + mf * 16 + gid;
#pragma unroll
                for (int nf = 0; nf < 4; nf++) {
                    const int c = n0 + wn + nf * 8 + 2 * tig;
                    *(uint32_t*)&Ch[(long long)r0 * 2048 + c] =
                        pack_half2(acc[mf][nf][0] * s, acc[mf][nf][1] * s);
                    *(uint32_t*)&Ch[(long long)(r0 + 8) * 2048 + c] =
                        pack_half2(acc[mf][nf][2] * s, acc[mf][nf][3] * s);
                }
            }
        } else {
#pragma unroll
            for (int mf = 0; mf < 4; mf++) {
                const int r0 = m0 + wm + mf * 16 + gid;
#pragma unroll
                for (int nf = 0; nf < 4; nf++) {
                    const long long cv = n0 + wn + nf * 8 + 2 * tig - 2048;
                    VT[cv * M_ + r0]           = __float2half_rn(acc[mf][nf][0]);
                    VT[(cv + 1) * M_ + r0]     = __float2half_rn(acc[mf][nf][1]);
                    VT[cv * M_ + r0 + 8]       = __float2half_rn(acc[mf][nf][2]);
                    VT[(cv + 1) * M_ + r0 + 8] = __float2half_rn(acc[mf][nf][3]);
                }
            }
        }
    }
}

// ===========================================================================
// Causal flash attention, fp16 m16n8k16.
// R16: FA3-style two-tile compute pipeline per warp:
//   iteration t:  softmax_t (sfr->pa)  ->  [wait/sync/issue]  ->
//                 S_{t+1} (refills sfr)  ->  PV_t (uses pa)
// so the scalar softmax overlaps the PV_{t-1} HMMA drain and S_{t+1}
// HMMAs issue before PV_t — tensor pipe fed on both sides of the scalar
// stream. Register-neutral (pa+sfr coexisted already). Single barrier:
// issue kv_{t+2} after the sync targets stage (t-1)%3 whose last reader
// (PV_{t-1}) precedes the sync in program order.
// 128-thread CTAs (4 warps, 64 q-rows), KT=64, 3-stage ring, 4 CTAs/SM.
// Lazy softmax-max (period 4), f16x2 ex2, l via ones-MMA. Heavy q first.
// Grid (S/64, H, B).
// ===========================================================================
constexpr int ATT_Q_B     = 64 * 128;             // 8192
constexpr int ATT_KV_B    = 2 * 64 * 128;         // K + V one stage = 16384
constexpr int ATT_SMEM_BYTES = ATT_Q_B + 3 * ATT_KV_B;  // 57344 (56KB)

__device__ __forceinline__ void attn_issue_kv(
    const __half* __restrict__ qkvh, const __half* __restrict__ vth,
    uint32_t sbase, int stage, int k0, int h, int b, int tid) {
    uint32_t kst = sbase + ATT_Q_B + stage * ATT_KV_B;
    uint32_t vst = kst + 64 * 128;
    const long long bS = (long long)b * S_;
#pragma unroll
    for (int it = 0; it < 8; it++) {
        int idx = tid + (it & 3) * 128;    // 0..511
        int row = idx >> 3;                // 0..63
        int c   = idx & 7;
        uint32_t off = (uint32_t)(row * 8 + (c ^ (row & 7))) * 16;
        if (it < 4) {
            CP_ASYNC16(kst + off,
                       qkvh + (bS + k0 + row) * 2048 + 1024 + h * 64 + c * 8);
        } else {
            CP_ASYNC16(vst + off,
                       vth + (long long)(h * 64 + row) * M_ + bS + k0 + c * 8);
        }
    }
    CP_COMMIT();
}

__global__ void __launch_bounds__(128, 4) attn_h_kernel(
    const __half* __restrict__ qkvh, const __half* __restrict__ vth,
    __half* __restrict__ yh) {
    extern __shared__ char smc[];
    const uint32_t sbase = smem_u32(smc);

    const int tid  = threadIdx.x;
    const int w    = tid >> 5;                       // 0..3
    const int lane = tid & 31;
    const int gid  = lane >> 2;
    const int tig  = lane & 3;
    const int qt   = gridDim.x - 1 - blockIdx.x;     // heavy tiles first
    const int h    = blockIdx.y;
    const int b    = blockIdx.z;
    const int q0   = qt * 64;
    const int nt   = qt + 1;                         // 64-key tiles
    const long long bS = (long long)b * S_;

    const int rl = lane & 7;
    const uint32_t q_lane  = (uint32_t)((w * 16 + ((lane >> 3) & 1) * 8 + rl) * 128);
    const int      q_cb    = lane >> 4;
    const uint32_t kv_lane = (uint32_t)((((lane >> 4) & 1) * 8 + rl) * 128);
    const int      kv_cb   = (lane >> 3) & 1;

    // prologue: groups [kv0][Q][kv1]
    attn_issue_kv(qkvh, vth, sbase, 0, 0, h, b, tid);
#pragma unroll
    for (int it = 0; it < 4; it++) {
        int idx = tid + it * 128;          // 0..511
        int row = idx >> 3;                // 0..63
        int c   = idx & 7;
        uint32_t off = (uint32_t)(row * 8 + (c ^ (row & 7))) * 16;
        CP_ASYNC16(sbase + off,
                   qkvh + (bS + q0 + row) * 2048 + h * 64 + c * 8);
    }
    CP_COMMIT();
    if (nt > 1) attn_issue_kv(qkvh, vth, sbase, 1, 64, h, b, tid);

    float m0r = -INFINITY, m1r = -INFINITY;        // running max (stale ok)
    float mc0 = -INFINITY, mc1 = -INFINITY;        // candidates since update
    float ofr[8][4] = {};
    float lfr[4] = {};                             // l via MMA
    float sfr[8][4];                               // S C-frags (tile in flight)
    const uint32_t ONES2[2] = {0x3C003C00u, 0x3C003C00u};  // half2(1,1)

    const int r0g = q0 + w * 16 + gid;
    const int r1g = r0g + 8;
    const int rfirst = q0 + w * 16;
    const int rmax   = rfirst + 15;

    // S-tile compute: Q (smem) x K (stage ksb) -> sfr
    auto computeS = [&](uint32_t ksb) {
#pragma unroll
        for (int nf = 0; nf < 8; nf++) {
            sfr[nf][0] = 0.f; sfr[nf][1] = 0.f;
            sfr[nf][2] = 0.f; sfr[nf][3] = 0.f;
        }
#pragma unroll
        for (int ks = 0; ks < 4; ks++) {
            uint32_t a[4];
            LDSM_X4(a[0], a[1], a[2], a[3],
                    sbase + q_lane + ((uint32_t)((2 * ks + q_cb) ^ rl) << 4));
            uint32_t bf[8][2];
#pragma unroll
            for (int j = 0; j < 4; j++) {
                uint32_t bd = ksb + kv_lane + j * 2048 +
                              ((uint32_t)((2 * ks + kv_cb) ^ rl) << 4);
                LDSM_X4(bf[2 * j][0], bf[2 * j][1],
                        bf[2 * j + 1][0], bf[2 * j + 1][1], bd);
            }
#pragma unroll
            for (int nf = 0; nf < 8; nf++)
                mma_f16(sfr[nf], a, bf[nf]);
        }
    };

    // prologue wait: kv0 + Q complete
    if (nt > 1) { CP_WAIT1(); } else { CP_WAIT0(); }
    __syncthreads();
    computeS(sbase + ATT_Q_B);            // S_0 from stage 0

    for (int t = 0; t < nt; t++) {
        const int k0 = t * 64;
        const bool act = (k0 <= rmax);
        uint32_t pa[4][4];

        if (act) {
            // causal mask for tile t (keys: c0,c1 -> 2tig, 2tig+1)
            if (k0 + 63 > rfirst) {
#pragma unroll
                for (int nf = 0; nf < 8; nf++) {
                    const int ca = k0 + nf * 8 + 2 * tig;
                    if (ca     > r0g) sfr[nf][0] = -INFINITY;
                    if (ca + 1 > r0g) sfr[nf][1] = -INFINITY;
                    if (ca     > r1g) sfr[nf][2] = -INFINITY;
                    if (ca + 1 > r1g) sfr[nf][3] = -INFINITY;
                }
            }
            // local max candidates (tree)
            {
                float a0[8], a1[8];
#pragma unroll
                for (int nf = 0; nf < 8; nf++) {
                    a0[nf] = fmaxf(sfr[nf][0], sfr[nf][1]);
                    a1[nf] = fmaxf(sfr[nf][2], sfr[nf][3]);
                }
#pragma unroll
                for (int srd = 4; srd; srd >>= 1)
#pragma unroll
                    for (int k = 0; k < srd; k++) {
                        a0[k] = fmaxf(a0[k], a0[k + srd]);
                        a1[k] = fmaxf(a1[k], a1[k + srd]);
                    }
                mc0 = fmaxf(mc0, a0[0]);
                mc1 = fmaxf(mc1, a1[0]);
            }
            // lazy update every 4th tile (waits on PV_{t-1} results via ofr)
            if ((t & 3) == 0) {
#pragma unroll
                for (int off = 1; off <= 2; off <<= 1) {
                    mc0 = fmaxf(mc0, __shfl_xor_sync(0xffffffffu, mc0, off));
                    mc1 = fmaxf(mc1, __shfl_xor_sync(0xffffffffu, mc1, off));
                }
                const float mn0 = fmaxf(m0r, mc0);
                const float mn1 = fmaxf(m1r, mc1);
                const float cr0 = ex2f(m0r - mn0);
                const float cr1 = ex2f(m1r - mn1);
                m0r = mn0; m1r = mn1;
                mc0 = -INFINITY; mc1 = -INFINITY;
#pragma unroll
                for (int nf = 0; nf < 8; nf++) {
                    ofr[nf][0] *= cr0; ofr[nf][1] *= cr0;
                    ofr[nf][2] *= cr1; ofr[nf][3] *= cr1;
                }
                lfr[0] *= cr0; lfr[1] *= cr0;
                lfr[2] *= cr1; lfr[3] *= cr1;
            }
            // P = 2^(s-m) -> pa; l via ones-MMA (sfr free after this)
#pragma unroll
            for (int j = 0; j < 4; j++) {
                pa[j][0] = h2ex2(pack_half2(sfr[2 * j][0] - m0r,
                                            sfr[2 * j][1] - m0r));
                pa[j][1] = h2ex2(pack_half2(sfr[2 * j][2] - m1r,
                                            sfr[2 * j][3] - m1r));
                pa[j][2] = h2ex2(pack_half2(sfr[2 * j + 1][0] - m0r,
                                            sfr[2 * j + 1][1] - m0r));
                pa[j][3] = h2ex2(pack_half2(sfr[2 * j + 1][2] - m1r,
                                            sfr[2 * j + 1][3] - m1r));
                mma_f16(lfr, pa[j], ONES2);
            }
        }

        // stage t+1 ready; issue kv_{t+2}; compute S_{t+1} (tensor work
        // interleaved before PV_t)
        if (t + 1 < nt) {
            CP_WAIT0();
            __syncthreads();   // stage t+1 visible AND all warps past PV_{t-1}
            if (t + 2 < nt)
                attn_issue_kv(qkvh, vth, sbase, (t + 2) % 3, (t + 2) * 64, h, b, tid);
            if ((t + 1) * 64 <= rmax)
                computeS(sbase + ATT_Q_B + (uint32_t)((t + 1) % 3) * ATT_KV_B);
        }

        // PV_t from stage t
        if (act) {
            const uint32_t vsb = sbase + ATT_Q_B + (uint32_t)(t % 3) * ATT_KV_B
                                 + 64 * 128;
#pragma unroll
            for (int j = 0; j < 4; j++) {
                uint32_t bf[8][2];
#pragma unroll
                for (int jb = 0; jb < 4; jb++) {
                    uint32_t bd = vsb + kv_lane + jb * 2048 +
                                  ((uint32_t)((2 * j + kv_cb) ^ rl) << 4);
                    LDSM_X4(bf[2 * jb][0], bf[2 * jb][1],
                            bf[2 * jb + 1][0], bf[2 * jb + 1][1], bd);
                }
#pragma unroll
                for (int nf = 0; nf < 8; nf++)
                    mma_f16(ofr[nf], pa[j], bf[nf]);
            }
        }
    }

    // epilogue: lane's lfr[0]/lfr[2] IS l for its two rows (2^-m cancels)
    const float inv0 = 1.0f / lfr[0];
    const float inv1 = 1.0f / lfr[2];
#pragma unroll
    for (int nf = 0; nf < 8; nf++) {
        const int c = h * 64 + nf * 8 + 2 * tig;
        *(uint32_t*)&yh[(bS + r0g) * E_ + c] =
            pack_half2(ofr[nf][0] * inv0, ofr[nf][1] * inv0);
        *(uint32_t*)&yh[(bS + r1g) * E_ + c] =
            pack_half2(ofr[nf][2] * inv1, ofr[nf][3] * inv1);
    }
}

// ===========================================================================
extern "C" void kernel_launch(void* const* d_in, const int* in_sizes, int n_in,
                              void* d_out, int out_size) {
    const float* x      = (const float*)d_in[0];   // [B, S, E]
    const float* w_att  = (const float*)d_in[1];   // [E, 3E]
    const float* w_proj = (const float*)d_in[2];   // [E, E]
    float* out = (float*)d_out;                    // [B, S, E]

    __half *xh, *qkvh, *vth, *yh, *wTh;
    cudaGetSymbolAddress((void**)&xh, g_xh);
    cudaGetSymbolAddress((void**)&qkvh, g_qkvh);
    cudaGetSymbolAddress((void**)&vth, g_vth);
    cudaGetSymbolAddress((void**)&yh, g_yh);
    cudaGetSymbolAddress((void**)&wTh, g_wTh);
    __half* wattTh  = wTh;                          // [3E, E]
    __half* wprojTh = wTh + (long long)3 * E_ * E_; // [E, E]

    cudaFuncSetAttribute(gemm_h_kernel,
                         cudaFuncAttributeMaxDynamicSharedMemorySize,
                         GEMM_SMEM_BYTES);
    cudaFuncSetAttribute(attn_h_kernel,
                         cudaFuncAttributeMaxDynamicSharedMemorySize,
                         ATT_SMEM_BYTES);

    // 0) Convert x; transpose+convert both weights (single launch)
    cvt_kernel<<<2048, 256>>>(x, xh, (long long)M_ * E_ / 4);
    {
        dim3 g(128, E_ / 32);
        transpose2_kernel<<<g, 256>>>(w_att, wattTh, w_proj, wprojTh);
    }
    // 1) QKV projection: Q (scaled) + K -> qkvh; V -> vth transposed
    {
        dim3 grid(3 * E_ / 128, M_ / 128);
        gemm_h_kernel<<<grid, 256, GEMM_SMEM_BYTES>>>(
            xh, wattTh, nullptr, qkvh, vth, M_, 3 * E_, E_, 1);
    }
    // 2) Causal flash attention -> yh (fp16), 64-q-row CTAs
    {
        dim3 grid(S_ / 64, H_, B_);
        attn_h_kernel<<<grid, 128, ATT_SMEM_BYTES>>>(qkvh, vth, yh);
    }
    // 3) Output projection -> fp32 out
    {
        dim3 grid(E_ / 128, M_ / 128);
        gemm_h_kernel<<<grid, 256, GEMM_SMEM_BYTES>>>(
            yh, wprojTh, out, nullptr, nullptr, M_, E_, E_, 0);
    }
}

// round 17
// speedup vs baseline: 1.0320x; 1.0320x over previous
#include <cuda_runtime.h>
#include <cuda_fp16.h>
#include <math.h>
#include <stdint.h>

// Problem constants
constexpr int B_ = 4;
constexpr int S_ = 2048;
constexpr int E_ = 1024;
constexpr int H_ = 16;
constexpr int D_ = 64;
constexpr int M_ = B_ * S_;   // 8192 tokens

// Q pre-scale: 1/sqrt(64) * log2(e)  (softmax runs in base-2)
#define QSCALE 0.180336880f

// Scratch (allocation-free rule: __device__ globals)
__device__ __half g_xh[(long long)M_ * E_];          // x in fp16
__device__ __half g_qkvh[(long long)M_ * 2 * E_];    // Q(pre-scaled)|K, fp16
__device__ __half g_vth[(long long)E_ * M_];         // V transposed [h*64+d][token]
__device__ __half g_yh[(long long)M_ * E_];          // attention out, fp16
__device__ __half g_wTh[(long long)3 * E_ * E_ + (long long)E_ * E_]; // W^T fp16

__device__ __forceinline__ float ex2f(float x) {
    float r; asm("ex2.approx.f32 %0, %1;" : "=f"(r) : "f"(x)); return r;
}
__device__ __forceinline__ uint32_t h2ex2(uint32_t x) {   // ex2 on packed half2
    uint32_t r; asm("ex2.approx.f16x2 %0, %1;" : "=r"(r) : "r"(x)); return r;
}
__device__ __forceinline__ uint32_t pack_half2(float lo, float hi) {
    uint32_t r;
    asm("cvt.rn.f16x2.f32 %0, %1, %2;" : "=r"(r) : "f"(hi), "f"(lo));
    return r;
}
__device__ __forceinline__ uint32_t smem_u32(const void* p) {
    uint32_t a;
    asm("{ .reg .u64 t; cvta.to.shared.u64 t, %1; cvt.u32.u64 %0, t; }"
        : "=r"(a) : "l"(p));
    return a;
}

#define CP_ASYNC16(dst, src) \
    asm volatile("cp.async.cg.shared.global [%0], [%1], 16;" \
        :: "r"(dst), "l"(src))
#define CP_COMMIT() asm volatile("cp.async.commit_group;" ::: "memory")
#define CP_WAIT0()  asm volatile("cp.async.wait_group 0;" ::: "memory")
#define CP_WAIT1()  asm volatile("cp.async.wait_group 1;" ::: "memory")

#define LDSM_X4(r0, r1, r2, r3, addr) \
    asm volatile("ldmatrix.sync.aligned.m8n8.x4.shared.b16 {%0,%1,%2,%3}, [%4];" \
        : "=r"(r0), "=r"(r1), "=r"(r2), "=r"(r3) : "r"(addr))

// m16n8k16 fp16 MMA, fp32 accumulate (sm_80+; Blackwell tensor pipe)
__device__ __forceinline__ void mma_f16(float d[4], const uint32_t a[4],
                                        const uint32_t b[2]) {
    asm volatile(
        "mma.sync.aligned.m16n8k16.row.col.f32.f16.f16.f32 "
        "{%0,%1,%2,%3}, {%4,%5,%6,%7}, {%8,%9}, {%0,%1,%2,%3};\n"
        : "+f"(d[0]), "+f"(d[1]), "+f"(d[2]), "+f"(d[3])
        : "r"(a[0]), "r"(a[1]), "r"(a[2]), "r"(a[3]), "r"(b[0]), "r"(b[1]));
}

// ===========================================================================
// x -> fp16
// ===========================================================================
__global__ void __launch_bounds__(256) cvt_kernel(
    const float* __restrict__ X, __half* __restrict__ XH, long long n4) {
    long long i = blockIdx.x * 256 + threadIdx.x;
    long long stride = (long long)gridDim.x * 256;
    for (; i < n4; i += stride) {
        float4 v = ((const float4*)X)[i];
        ((uint2*)XH)[i] = make_uint2(pack_half2(v.x, v.y), pack_half2(v.z, v.w));
    }
}

// ===========================================================================
// Fused weight transpose + fp16 for BOTH weights in one launch.
// blocks x in [0,96): w_att (N=3072); [96,128): w_proj (N=1024). K=1024.
// ===========================================================================
__global__ void __launch_bounds__(256) transpose2_kernel(
    const float* __restrict__ Wa, __half* __restrict__ WaT,
    const float* __restrict__ Wp, __half* __restrict__ WpT) {
    __shared__ float t[32][33];
    const bool isA = (blockIdx.x < 96);
    const float* W = isA ? Wa : Wp;
    __half* WT     = isA ? WaT : WpT;
    const int N    = isA ? 3 * E_ : E_;
    const int n0   = (isA ? blockIdx.x : blockIdx.x - 96) * 32;
    const int k0   = blockIdx.y * 32;
    const int tx = threadIdx.x & 31, ty = threadIdx.x >> 5;
    for (int r = ty; r < 32; r += 8)
        t[r][tx] = W[(long long)(k0 + r) * N + n0 + tx];
    __syncthreads();
    for (int r = ty; r < 32; r += 8)
        WT[(long long)(n0 + r) * E_ + k0 + tx] = __float2half_rn(t[tx][r]);
}

// ===========================================================================
// fp16 mma.sync GEMM, 3-stage cp.async pipeline, ldmatrix fragment loads.
// C = A[M,K] @ BT[N,K]^T, fp16 operands, fp32 accum.
// 128x128x64 tile (BK=64 halves = 128B rows), 8 warps (2x4), warp 64x32.
// mode 0: fp32 out to Cf.
// mode 1 (QKV): n0<1024 -> Q (scale by QSCALE, half -> Ch);
//               n0<2048 -> K (half -> Ch); else V -> VT transposed.
// ===========================================================================
constexpr int BK = 64;                          // halves per chunk (128B)
constexpr int GSTAGE_B = 2 * 128 * 128;         // A + B tile bytes = 32768
constexpr int GEMM_SMEM_BYTES = 3 * GSTAGE_B;   // 98304

__device__ __forceinline__ void gemm_issue(
    const __half* __restrict__ A, const __half* __restrict__ BT,
    uint32_t sbase, int stage, int m0, int n0, int k0, int K, int tid) {
    uint32_t st = sbase + stage * GSTAGE_B;
#pragma unroll
    for (int it = 0; it < 4; it++) {
        int idx = tid + it * 256;          // 0..1023
        int row = idx >> 3;                // 0..127
        int c   = idx & 7;                 // 16B chunk
        uint32_t off = (uint32_t)(row * 8 + (c ^ (row & 7))) * 16;
        CP_ASYNC16(st + off, A + (long long)(m0 + row) * K + k0 + c * 8);
        CP_ASYNC16(st + 16384 + off, BT + (long long)(n0 + row) * K + k0 + c * 8);
    }
    CP_COMMIT();
}

__global__ void __launch_bounds__(256, 2) gemm_h_kernel(
    const __half* __restrict__ A, const __half* __restrict__ BT,
    float* __restrict__ Cf, __half* __restrict__ Ch, __half* __restrict__ VT,
    int M, int N, int K, int mode) {
    extern __shared__ char smc[];
    const uint32_t sbase = smem_u32(smc);

    const int tid  = threadIdx.x;
    const int wid  = tid >> 5;
    const int lane = tid & 31;
    const int gid  = lane >> 2;
    const int tig  = lane & 3;
    const int wm   = (wid & 1) * 64;
    const int wn   = (wid >> 1) * 32;
    const int m0   = blockIdx.y * 128;
    const int n0   = blockIdx.x * 128;

    const int rl = lane & 7;
    const uint32_t a_lane = (uint32_t)((wm + ((lane >> 3) & 1) * 8 + rl) * 128);
    const int a_cb = lane >> 4;
    const uint32_t b_lane = 16384u + (uint32_t)((wn + ((lane >> 4) & 1) * 8 + rl) * 128);
    const int b_cb = (lane >> 3) & 1;

    float acc[4][4][4] = {};

    const int NIT = K / BK;
    gemm_issue(A, BT, sbase, 0, m0, n0, 0, K, tid);
    gemm_issue(A, BT, sbase, 1, m0, n0, BK, K, tid);

    for (int i = 0; i < NIT; i++) {
        if (i + 1 < NIT) { CP_WAIT1(); } else { CP_WAIT0(); }
        __syncthreads();
        if (i + 2 < NIT)
            gemm_issue(A, BT, sbase, (i + 2) % 3, m0, n0, (i + 2) * BK, K, tid);

        const uint32_t stb = sbase + (uint32_t)(i % 3) * GSTAGE_B;
#pragma unroll
        for (int ks = 0; ks < 4; ks++) {       // 4 k16 steps per BK=64
            uint32_t af[4][4], bf[4][2];
#pragma unroll
            for (int mf = 0; mf < 4; mf++) {
                uint32_t ad = stb + a_lane + mf * 2048 +
                              ((uint32_t)((2 * ks + a_cb) ^ rl) << 4);
                LDSM_X4(af[mf][0], af[mf][1], af[mf][2], af[mf][3], ad);
            }
#pragma unroll
            for (int j = 0; j < 2; j++) {
                uint32_t bd = stb + b_lane + j * 2048 +
                              ((uint32_t)((2 * ks + b_cb) ^ rl) << 4);
                LDSM_X4(bf[2 * j][0], bf[2 * j][1], bf[2 * j + 1][0], bf[2 * j + 1][1], bd);
            }
#pragma unroll
            for (int mf = 0; mf < 4; mf++)
#pragma unroll
                for (int nf = 0; nf < 4; nf++)
                    mma_f16(acc[mf][nf], af[mf], bf[nf]);
        }
    }

    // epilogue
    if (mode == 0) {
#pragma unroll
        for (int mf = 0; mf < 4; mf++) {
            const int r0 = m0 + wm + mf * 16 + gid;
#pragma unroll
            for (int nf = 0; nf < 4; nf++) {
                const int c = n0 + wn + nf * 8 + 2 * tig;
                *(float2*)&Cf[(long long)r0 * N + c] =
                    make_float2(acc[mf][nf][0], acc[mf][nf][1]);
                *(float2*)&Cf[(long long)(r0 + 8) * N + c] =
                    make_float2(acc[mf][nf][2], acc[mf][nf][3]);
            }
        }
    } else {
        const int region = n0 >> 10;   // 0:Q 1:K 2:V
        if (region < 2) {
            const float s = (region == 0) ? QSCALE : 1.0f;
#pragma unroll
            for (int mf = 0; mf < 4; mf++) {
                const int r0 = m0 + wm + mf * 16 + gid;
#pragma unroll
                for (int nf = 0; nf < 4; nf++) {
                    const int c = n0 + wn + nf * 8 + 2 * tig;
                    *(uint32_t*)&Ch[(long long)r0 * 2048 + c] =
                        pack_half2(acc[mf][nf][0] * s, acc[mf][nf][1] * s);
                    *(uint32_t*)&Ch[(long long)(r0 + 8) * 2048 + c] =
                        pack_half2(acc[mf][nf][2] * s, acc[mf][nf][3] * s);
                }
            }
        } else {
#pragma unroll
            for (int mf = 0; mf < 4; mf++) {
                const int r0 = m0 + wm + mf * 16 + gid;
#pragma unroll
                for (int nf = 0; nf < 4; nf++) {
                    const long long cv = n0 + wn + nf * 8 + 2 * tig - 2048;
                    VT[cv * M_ + r0]           = __float2half_rn(acc[mf][nf][0]);
                    VT[(cv + 1) * M_ + r0]     = __float2half_rn(acc[mf][nf][1]);
                    VT[cv * M_ + r0 + 8]       = __float2half_rn(acc[mf][nf][2]);
                    VT[(cv + 1) * M_ + r0 + 8] = __float2half_rn(acc[mf][nf][3]);
                }
            }
        }
    }
}

// ===========================================================================
// Causal flash attention, fp16 m16n8k16.
// R17: R15 schedule (best so far) + Q fragments HOISTED into registers:
// Q is loop-invariant but ptxas cannot hoist LDSM across __syncthreads,
// so load qa[4][4] once after the prologue wait and drop the per-tile
// Q ldmatrix (4 of 9 LDSM_X4 per tile).
// 128-thread CTAs (4 warps, 64 q-rows), KT=64, 3-stage ring, 4 CTAs/SM.
// Lazy softmax-max (period 4) with fmax tree; exp via f16x2 ex2 -> P
// A-frags; l via ones-MMA. Heavy q-tiles first. Grid (S/64, H, B).
// ===========================================================================
constexpr int ATT_Q_B     = 64 * 128;             // 8192
constexpr int ATT_KV_B    = 2 * 64 * 128;         // K + V one stage = 16384
constexpr int ATT_SMEM_BYTES = ATT_Q_B + 3 * ATT_KV_B;  // 57344 (56KB)

__device__ __forceinline__ void attn_issue_kv(
    const __half* __restrict__ qkvh, const __half* __restrict__ vth,
    uint32_t sbase, int stage, int k0, int h, int b, int tid) {
    uint32_t kst = sbase + ATT_Q_B + stage * ATT_KV_B;
    uint32_t vst = kst + 64 * 128;
    const long long bS = (long long)b * S_;
#pragma unroll
    for (int it = 0; it < 8; it++) {
        int idx = tid + (it & 3) * 128;    // 0..511
        int row = idx >> 3;                // 0..63
        int c   = idx & 7;
        uint32_t off = (uint32_t)(row * 8 + (c ^ (row & 7))) * 16;
        if (it < 4) {
            CP_ASYNC16(kst + off,
                       qkvh + (bS + k0 + row) * 2048 + 1024 + h * 64 + c * 8);
        } else {
            CP_ASYNC16(vst + off,
                       vth + (long long)(h * 64 + row) * M_ + bS + k0 + c * 8);
        }
    }
    CP_COMMIT();
}

__global__ void __launch_bounds__(128, 4) attn_h_kernel(
    const __half* __restrict__ qkvh, const __half* __restrict__ vth,
    __half* __restrict__ yh) {
    extern __shared__ char smc[];
    const uint32_t sbase = smem_u32(smc);

    const int tid  = threadIdx.x;
    const int w    = tid >> 5;                       // 0..3
    const int lane = tid & 31;
    const int gid  = lane >> 2;
    const int tig  = lane & 3;
    const int qt   = gridDim.x - 1 - blockIdx.x;     // heavy tiles first
    const int h    = blockIdx.y;
    const int b    = blockIdx.z;
    const int q0   = qt * 64;
    const int nt   = qt + 1;                         // 64-key tiles
    const long long bS = (long long)b * S_;

    const int rl = lane & 7;
    const uint32_t q_lane  = (uint32_t)((w * 16 + ((lane >> 3) & 1) * 8 + rl) * 128);
    const int      q_cb    = lane >> 4;
    const uint32_t kv_lane = (uint32_t)((((lane >> 4) & 1) * 8 + rl) * 128);
    const int      kv_cb   = (lane >> 3) & 1;

    // prologue: groups [kv0][Q][kv1]
    attn_issue_kv(qkvh, vth, sbase, 0, 0, h, b, tid);
#pragma unroll
    for (int it = 0; it < 4; it++) {
        int idx = tid + it * 128;          // 0..511
        int row = idx >> 3;                // 0..63
        int c   = idx & 7;
        uint32_t off = (uint32_t)(row * 8 + (c ^ (row & 7))) * 16;
        CP_ASYNC16(sbase + off,
                   qkvh + (bS + q0 + row) * 2048 + h * 64 + c * 8);
    }
    CP_COMMIT();
    if (nt > 1) attn_issue_kv(qkvh, vth, sbase, 1, 64, h, b, tid);

    // hoist Q fragments into registers (loop-invariant; ptxas can't hoist
    // LDSM across barriers itself)
    uint32_t qa[4][4];
    if (nt > 1) { CP_WAIT1(); } else { CP_WAIT0(); }
    __syncthreads();
#pragma unroll
    for (int ks = 0; ks < 4; ks++)
        LDSM_X4(qa[ks][0], qa[ks][1], qa[ks][2], qa[ks][3],
                sbase + q_lane + ((uint32_t)((2 * ks + q_cb) ^ rl) << 4));

    float m0r = -INFINITY, m1r = -INFINITY;        // running max (stale ok)
    float mc0 = -INFINITY, mc1 = -INFINITY;        // candidates since update
    float ofr[8][4] = {};
    float lfr[4] = {};                             // l via MMA
    const uint32_t ONES2[2] = {0x3C003C00u, 0x3C003C00u};  // half2(1,1)

    const int r0g = q0 + w * 16 + gid;
    const int r1g = r0g + 8;
    const int rfirst = q0 + w * 16;

    for (int t = 0; t < nt; t++) {
        const int k0 = t * 64;
        if (t + 1 < nt) { CP_WAIT1(); } else { CP_WAIT0(); }
        __syncthreads();   // stage t ready AND stage (t-1)%3 readers done
        if (t + 2 < nt)
            attn_issue_kv(qkvh, vth, sbase, (t + 2) % 3, (t + 2) * 64, h, b, tid);

        const uint32_t ksb = sbase + ATT_Q_B + (uint32_t)(t % 3) * ATT_KV_B;
        const uint32_t vsb = ksb + 64 * 128;

        // S = Q K^T  (Q from registers; 4 k16 steps over d=64)
        float sfr[8][4] = {};
#pragma unroll
        for (int ks = 0; ks < 4; ks++) {
            uint32_t bf[8][2];
#pragma unroll
            for (int j = 0; j < 4; j++) {
                uint32_t bd = ksb + kv_lane + j * 2048 +
                              ((uint32_t)((2 * ks + kv_cb) ^ rl) << 4);
                LDSM_X4(bf[2 * j][0], bf[2 * j][1],
                        bf[2 * j + 1][0], bf[2 * j + 1][1], bd);
            }
#pragma unroll
            for (int nf = 0; nf < 8; nf++)
                mma_f16(sfr[nf], qa[ks], bf[nf]);
        }

        // causal mask (keys natural: c0,c1 -> 2tig, 2tig+1); gate on
        // the FIRST row of the warp strip (only diagonal tile masks).
        if (k0 + 63 > rfirst) {
#pragma unroll
            for (int nf = 0; nf < 8; nf++) {
                const int ca = k0 + nf * 8 + 2 * tig;
                if (ca     > r0g) sfr[nf][0] = -INFINITY;
                if (ca + 1 > r0g) sfr[nf][1] = -INFINITY;
                if (ca     > r1g) sfr[nf][2] = -INFINITY;
                if (ca + 1 > r1g) sfr[nf][3] = -INFINITY;
            }
        }

        // accumulate local max candidates (explicit tree, depth ~5)
        {
            float a0[8], a1[8];
#pragma unroll
            for (int nf = 0; nf < 8; nf++) {
                a0[nf] = fmaxf(sfr[nf][0], sfr[nf][1]);
                a1[nf] = fmaxf(sfr[nf][2], sfr[nf][3]);
            }
#pragma unroll
            for (int srd = 4; srd; srd >>= 1)
#pragma unroll
                for (int k = 0; k < srd; k++) {
                    a0[k] = fmaxf(a0[k], a0[k + srd]);
                    a1[k] = fmaxf(a1[k], a1[k + srd]);
                }
            mc0 = fmaxf(mc0, a0[0]);
            mc1 = fmaxf(mc1, a1[0]);
        }

        // lazy update: shfl-reduce + rescale every 4th tile
        if ((t & 3) == 0) {
#pragma unroll
            for (int off = 1; off <= 2; off <<= 1) {
                mc0 = fmaxf(mc0, __shfl_xor_sync(0xffffffffu, mc0, off));
                mc1 = fmaxf(mc1, __shfl_xor_sync(0xffffffffu, mc1, off));
            }
            const float mn0 = fmaxf(m0r, mc0);
            const float mn1 = fmaxf(m1r, mc1);
            const float cr0 = ex2f(m0r - mn0);   // t=0: ex2(-inf)=0, O/l are 0
            const float cr1 = ex2f(m1r - mn1);
            m0r = mn0; m1r = mn1;
            mc0 = -INFINITY; mc1 = -INFINITY;
#pragma unroll
            for (int nf = 0; nf < 8; nf++) {
                ofr[nf][0] *= cr0; ofr[nf][1] *= cr0;
                ofr[nf][2] *= cr1; ofr[nf][3] *= cr1;
            }
            lfr[0] *= cr0; lfr[1] *= cr0;
            lfr[2] *= cr1; lfr[3] *= cr1;
        }

        // P = 2^(s-m) via f16x2 ex2 -> A-frags; l via ones-MMA.
        // Stale m bounded (~2^6) -> safe in fp16; scale cancels in O/l.
        uint32_t pa[4][4];
#pragma unroll
        for (int j = 0; j < 4; j++) {
            pa[j][0] = h2ex2(pack_half2(sfr[2 * j][0] - m0r,
                                        sfr[2 * j][1] - m0r));
            pa[j][1] = h2ex2(pack_half2(sfr[2 * j][2] - m1r,
                                        sfr[2 * j][3] - m1r));
            pa[j][2] = h2ex2(pack_half2(sfr[2 * j + 1][0] - m0r,
                                        sfr[2 * j + 1][1] - m0r));
            pa[j][3] = h2ex2(pack_half2(sfr[2 * j + 1][2] - m1r,
                                        sfr[2 * j + 1][3] - m1r));
            mma_f16(lfr, pa[j], ONES2);
        }

        // O += P @ V  (V B-frags from Vt[d][key] tile)
#pragma unroll
        for (int j = 0; j < 4; j++) {
            uint32_t bf[8][2];
#pragma unroll
            for (int jb = 0; jb < 4; jb++) {
                uint32_t bd = vsb + kv_lane + jb * 2048 +
                              ((uint32_t)((2 * j + kv_cb) ^ rl) << 4);
                LDSM_X4(bf[2 * jb][0], bf[2 * jb][1],
                        bf[2 * jb + 1][0], bf[2 * jb + 1][1], bd);
            }
#pragma unroll
            for (int nf = 0; nf < 8; nf++)
                mma_f16(ofr[nf], pa[j], bf[nf]);
        }
    }

    // epilogue: lane's lfr[0]/lfr[2] IS l for its two rows (2^-m cancels)
    const float inv0 = 1.0f / lfr[0];
    const float inv1 = 1.0f / lfr[2];
#pragma unroll
    for (int nf = 0; nf < 8; nf++) {
        const int c = h * 64 + nf * 8 + 2 * tig;
        *(uint32_t*)&yh[(bS + r0g) * E_ + c] =
            pack_half2(ofr[nf][0] * inv0, ofr[nf][1] * inv0);
        *(uint32_t*)&yh[(bS + r1g) * E_ + c] =
            pack_half2(ofr[nf][2] * inv1, ofr[nf][3] * inv1);
    }
}

// ===========================================================================
extern "C" void kernel_launch(void* const* d_in, const int* in_sizes, int n_in,
                              void* d_out, int out_size) {
    const float* x      = (const float*)d_in[0];   // [B, S, E]
    const float* w_att  = (const float*)d_in[1];   // [E, 3E]
    const float* w_proj = (const float*)d_in[2];   // [E, E]
    float* out = (float*)d_out;                    // [B, S, E]

    __half *xh, *qkvh, *vth, *yh, *wTh;
    cudaGetSymbolAddress((void**)&xh, g_xh);
    cudaGetSymbolAddress((void**)&qkvh, g_qkvh);
    cudaGetSymbolAddress((void**)&vth, g_vth);
    cudaGetSymbolAddress((void**)&yh, g_yh);
    cudaGetSymbolAddress((void**)&wTh, g_wTh);
    __half* wattTh  = wTh;                          // [3E, E]
    __half* wprojTh = wTh + (long long)3 * E_ * E_; // [E, E]

    cudaFuncSetAttribute(gemm_h_kernel,
                         cudaFuncAttributeMaxDynamicSharedMemorySize,
                         GEMM_SMEM_BYTES);
    cudaFuncSetAttribute(attn_h_kernel,
                         cudaFuncAttributeMaxDynamicSharedMemorySize,
                         ATT_SMEM_BYTES);

    // 0) Convert x; transpose+convert both weights (single launch)
    cvt_kernel<<<2048, 256>>>(x, xh, (long long)M_ * E_ / 4);
    {
        dim3 g(128, E_ / 32);
        transpose2_kernel<<<g, 256>>>(w_att, wattTh, w_proj, wprojTh);
    }
    // 1) QKV projection: Q (scaled) + K -> qkvh; V -> vth transposed
    {
        dim3 grid(3 * E_ / 128, M_ / 128);
        gemm_h_kernel<<<grid, 256, GEMM_SMEM_BYTES>>>(
            xh, wattTh, nullptr, qkvh, vth, M_, 3 * E_, E_, 1);
    }
    // 2) Causal flash attention -> yh (fp16), 64-q-row CTAs
    {
        dim3 grid(S_ / 64, H_, B_);
        attn_h_kernel<<<grid, 128, ATT_SMEM_BYTES>>>(qkvh, vth, yh);
    }
    // 3) Output projection -> fp32 out
    {
        dim3 grid(E_ / 128, M_ / 128);
        gemm_h_kernel<<<grid, 256, GEMM_SMEM_BYTES>>>(
            yh, wprojTh, out, nullptr, nullptr, M_, E_, E_, 0);
    }
}